// round 12
// baseline (speedup 1.0000x reference)
#include <cuda_runtime.h>

#define N_ENT  50000
#define C      128
#define N_RELM 10          // N_REL - 1
#define EPS    1e-12f

// Scratch (no allocation allowed).
__device__ float    g_bufA[(size_t)N_ENT * C];
__device__ float    g_bufB[(size_t)N_ENT * C];
__device__ int      g_cnt[N_ENT];
__device__ int      g_fill[N_ENT];
__device__ int      g_off[N_ENT + 1];
__device__ unsigned g_sorted[1600000];   // tail | (rel << 16)

// ---------------------------------------------------------------------------
// Histogram of heads, 4 edges per thread (int4) for MLP on the atomics.
// ---------------------------------------------------------------------------
__global__ void hist_kernel(const int* __restrict__ edge_index, int E4) {
    int i = blockIdx.x * blockDim.x + threadIdx.x;
    if (i >= E4) return;
    int4 h4 = __ldg(reinterpret_cast<const int4*>(edge_index) + i);
    atomicAdd(&g_cnt[h4.x], 1);
    atomicAdd(&g_cnt[h4.y], 1);
    atomicAdd(&g_cnt[h4.z], 1);
    atomicAdd(&g_cnt[h4.w], 1);
}

// ---------------------------------------------------------------------------
// Single-block exclusive scan g_cnt -> g_off; g_fill gets a mutable copy.
// ---------------------------------------------------------------------------
__global__ void scan_kernel() {
    const int T = 1024;
    __shared__ int sh[T];
    int tid = threadIdx.x;
    const int chunk = (N_ENT + T - 1) / T;
    int begin = tid * chunk;
    int endi  = begin + chunk; if (endi > N_ENT) endi = N_ENT;
    if (begin > N_ENT) begin = N_ENT;

    int sum = 0;
    for (int i = begin; i < endi; i++) sum += g_cnt[i];
    sh[tid] = sum;
    __syncthreads();
    for (int o = 1; o < T; o <<= 1) {
        int v = (tid >= o) ? sh[tid - o] : 0;
        __syncthreads();
        sh[tid] += v;
        __syncthreads();
    }
    int run = (tid == 0) ? 0 : sh[tid - 1];
    for (int i = begin; i < endi; i++) {
        g_off[i]  = run;
        g_fill[i] = run;     // mutable cursor for build
        run += g_cnt[i];
    }
    if (tid == T - 1) g_off[N_ENT] = run;   // == E
}

// ---------------------------------------------------------------------------
// Scatter edges into CSR order, 4 edges per thread (independent chains).
// Packs (tail, rel) into one uint: tail < 65536 fits 16 bits; rel in [0,9].
// ---------------------------------------------------------------------------
__global__ void build_kernel(const int* __restrict__ edge_index,
                             const int* __restrict__ edge_type,
                             int E4, int E) {
    int i = blockIdx.x * blockDim.x + threadIdx.x;
    if (i >= E4) return;
    int4 h4 = __ldg(reinterpret_cast<const int4*>(edge_index) + i);
    int4 t4 = __ldg(reinterpret_cast<const int4*>(edge_index) + (E >> 2) + i);
    int4 r4 = __ldg(reinterpret_cast<const int4*>(edge_type) + i);
    int p0 = atomicAdd(&g_fill[h4.x], 1);
    int p1 = atomicAdd(&g_fill[h4.y], 1);
    int p2 = atomicAdd(&g_fill[h4.z], 1);
    int p3 = atomicAdd(&g_fill[h4.w], 1);
    g_sorted[p0] = (unsigned)t4.x | ((unsigned)(r4.x - 1) << 16);
    g_sorted[p1] = (unsigned)t4.y | ((unsigned)(r4.y - 1) << 16);
    g_sorted[p2] = (unsigned)t4.z | ((unsigned)(r4.z - 1) << 16);
    g_sorted[p3] = (unsigned)t4.w | ((unsigned)(r4.w - 1) << 16);
}

// ---------------------------------------------------------------------------
// One hop, fully fused: warp per head, no atomics.
//   acc = mean over segment of emb_in[tail] * weight[rel]; L2-normalize;
//   emb_out[h] = acc;
//   FIRST: res[h] = base[h] + acc   (folds the res=emb memcpy)
//   else : res[h] += acc
// ---------------------------------------------------------------------------
template <bool FIRST>
__global__ void __launch_bounds__(256)
hop_kernel(const float* __restrict__ emb_in,
           const float* __restrict__ weight,
           float* __restrict__ emb_out,
           float* __restrict__ res,
           const float* __restrict__ base) {
    __shared__ float4 wsh[N_RELM * 32];   // 10 relations x 128 ch = 5 KB
    {
        float* wf = reinterpret_cast<float*>(wsh);
        for (int i = threadIdx.x; i < N_RELM * C; i += 256) wf[i] = weight[i];
    }
    __syncthreads();

    int head = blockIdx.x * 8 + (threadIdx.x >> 5);
    int lane = threadIdx.x & 31;
    if (head >= N_ENT) return;

    int start = g_off[head];
    int end   = g_off[head + 1];

    float4 acc = make_float4(0.f, 0.f, 0.f, 0.f);

    int e = start;
    for (; e + 4 <= end; e += 4) {
        unsigned p0 = g_sorted[e + 0];
        unsigned p1 = g_sorted[e + 1];
        unsigned p2 = g_sorted[e + 2];
        unsigned p3 = g_sorted[e + 3];
        float4 v0 = __ldg(reinterpret_cast<const float4*>(emb_in + (size_t)(p0 & 0xFFFFu) * C) + lane);
        float4 v1 = __ldg(reinterpret_cast<const float4*>(emb_in + (size_t)(p1 & 0xFFFFu) * C) + lane);
        float4 v2 = __ldg(reinterpret_cast<const float4*>(emb_in + (size_t)(p2 & 0xFFFFu) * C) + lane);
        float4 v3 = __ldg(reinterpret_cast<const float4*>(emb_in + (size_t)(p3 & 0xFFFFu) * C) + lane);
        float4 w0 = wsh[(p0 >> 16) * 32 + lane];
        float4 w1 = wsh[(p1 >> 16) * 32 + lane];
        float4 w2 = wsh[(p2 >> 16) * 32 + lane];
        float4 w3 = wsh[(p3 >> 16) * 32 + lane];
        acc.x += v0.x * w0.x; acc.y += v0.y * w0.y; acc.z += v0.z * w0.z; acc.w += v0.w * w0.w;
        acc.x += v1.x * w1.x; acc.y += v1.y * w1.y; acc.z += v1.z * w1.z; acc.w += v1.w * w1.w;
        acc.x += v2.x * w2.x; acc.y += v2.y * w2.y; acc.z += v2.z * w2.z; acc.w += v2.w * w2.w;
        acc.x += v3.x * w3.x; acc.y += v3.y * w3.y; acc.z += v3.z * w3.z; acc.w += v3.w * w3.w;
    }
    for (; e < end; e++) {
        unsigned p = g_sorted[e];
        float4 v = __ldg(reinterpret_cast<const float4*>(emb_in + (size_t)(p & 0xFFFFu) * C) + lane);
        float4 w = wsh[(p >> 16) * 32 + lane];
        acc.x += v.x * w.x; acc.y += v.y * w.y; acc.z += v.z * w.z; acc.w += v.w * w.w;
    }

    // scatter_mean
    float inv_d = 1.0f / fmaxf((float)(end - start), 1.0f);
    acc.x *= inv_d; acc.y *= inv_d; acc.z *= inv_d; acc.w *= inv_d;

    // L2 normalize
    float s = acc.x * acc.x + acc.y * acc.y + acc.z * acc.z + acc.w * acc.w;
    #pragma unroll
    for (int o = 16; o > 0; o >>= 1) s += __shfl_xor_sync(0xffffffff, s, o);
    float inv_n = 1.0f / fmaxf(sqrtf(s), EPS);
    acc.x *= inv_n; acc.y *= inv_n; acc.z *= inv_n; acc.w *= inv_n;

    // next-hop input
    reinterpret_cast<float4*>(emb_out + (size_t)head * C)[lane] = acc;

    // res accumulate
    float4* rrow = reinterpret_cast<float4*>(res + (size_t)head * C);
    float4 o4;
    if (FIRST) {
        o4 = __ldg(reinterpret_cast<const float4*>(base + (size_t)head * C) + lane);
    } else {
        o4 = rrow[lane];
    }
    o4.x += acc.x; o4.y += acc.y; o4.z += acc.z; o4.w += acc.w;
    rrow[lane] = o4;
}

// ---------------------------------------------------------------------------
// kernel_launch
// Inputs: entity_emb f32 [50000,128], edge_index i32 [2,E],
//         edge_type i32 [E], weight f32 [10,128]
// Output: f32 [50000,128]
// ---------------------------------------------------------------------------
extern "C" void kernel_launch(void* const* d_in, const int* in_sizes, int n_in,
                              void* d_out, int out_size) {
    const float* emb = (const float*)d_in[0];
    const int*   ei  = (const int*)d_in[1];
    const int*   et  = (const int*)d_in[2];
    const float* w   = (const float*)d_in[3];
    float* out = (float*)d_out;

    const int E  = in_sizes[1] / 2;
    const int E4 = E / 4;              // E = 1.6M, divisible by 4

    void *pA = nullptr, *pB = nullptr, *pC = nullptr;
    cudaGetSymbolAddress(&pA, g_bufA);
    cudaGetSymbolAddress(&pB, g_bufB);
    cudaGetSymbolAddress(&pC, g_cnt);
    float* A = (float*)pA;
    float* B = (float*)pB;

    // ---- Build CSR (once; reused by all 3 hops) ----
    cudaMemsetAsync(pC, 0, N_ENT * sizeof(int));
    hist_kernel<<<(E4 + 255) / 256, 256>>>(ei, E4);
    scan_kernel<<<1, 1024>>>();
    build_kernel<<<(E4 + 255) / 256, 256>>>(ei, et, E4, E);

    // ---- 3 fused hops (hop 1 folds res = emb + n1) ----
    const int HOP_BLOCKS = (N_ENT + 7) / 8;   // warp per head, 8 warps/block
    hop_kernel<true ><<<HOP_BLOCKS, 256>>>(emb, w, A, out, emb);  // emb -> A
    hop_kernel<false><<<HOP_BLOCKS, 256>>>(A,   w, B, out, emb);  // A -> B
    hop_kernel<false><<<HOP_BLOCKS, 256>>>(B,   w, A, out, emb);  // B -> A
}